// round 5
// baseline (speedup 1.0000x reference)
#include <cuda_runtime.h>
#include <math.h>

#define BB 64
#define NN 4096
#define DD 256
#define SPLIT 8
#define CH (NN / SPLIT)     // 512 rows per flash CTA
#define NTILES (CH / 32)    // 16 tiles of 32 rows

#define NEG_HUGE (-1.0e38f)

// ---------------- scratch (device globals; no allocation allowed) ----------------
__device__ float g_c[BB * NN];                    // -0.5 * m^T P m
__device__ float g_z[BB * DD];                    // current z
__device__ float g_y[BB * DD];                    // y = 0.5 (P+P^T) z
__device__ float g_part[BB * SPLIT * (DD + 2)];   // per-split partials: [M, S, num[256]]
__device__ int   g_identity;                      // 1 if P == I
__device__ int   g_conv[BB];                      // per-b bitwise-converged flags
__device__ int   g_ten = 10;                      // fallback iteration count

// ---------------- init: flags + copy z ----------------
__global__ void k_init(const float* __restrict__ z_in) {
    int t = threadIdx.x;
    if (t == 0) g_identity = 1;
    if (t < BB) g_conv[t] = 0;
    for (int i = t; i < BB * DD; i += blockDim.x) g_z[i] = z_in[i];
}

// ---------------- check P == eye(D) ----------------
__global__ void k_check(const float* __restrict__ P) {
    int idx = blockIdx.x * blockDim.x + threadIdx.x;
    bool ok = true;
#pragma unroll
    for (int e = 0; e < 4; e++) {
        int q = idx * 4 + e;
        int i = q >> 8, j = q & 255;
        ok &= (P[q] == (i == j ? 1.0f : 0.0f));
    }
    int allok = __syncthreads_and((int)ok);
    if (!allok && threadIdx.x == 0) g_identity = 0;
}

// ---------------- y = 0.5 (P + P^T) z  (one CTA per b) ----------------
__global__ void k_y(const float* __restrict__ P) {
    int b = blockIdx.x, t = threadIdx.x;
    __shared__ float zs[DD];
    zs[t] = g_z[b * DD + t];
    __syncthreads();
    float acc = 0.f;
#pragma unroll 8
    for (int i = 0; i < DD; i++)
        acc += zs[i] * (P[i * DD + t] + P[t * DD + i]);
    g_y[b * DD + t] = 0.5f * acc;
}

// ---------------- c_n fast path: P == I -> c = -0.5 ||m||^2 ----------------
__global__ void __launch_bounds__(256) k_c_fast(const float* __restrict__ means) {
    if (!g_identity) return;
    int w = threadIdx.x >> 5, l = threadIdx.x & 31;
    int d0 = 4 * l, d1 = 128 + 4 * l;
#pragma unroll
    for (int k = 0; k < 4; k++) {
        int row = blockIdx.x * 32 + w + 8 * k;
        const float* mr = means + (size_t)row * DD;
        float4 a = *(const float4*)(mr + d0);
        float4 c4 = *(const float4*)(mr + d1);
        float acc = a.x * a.x + a.y * a.y + a.z * a.z + a.w * a.w +
                    c4.x * c4.x + c4.y * c4.y + c4.z * c4.z + c4.w * c4.w;
#pragma unroll
        for (int off = 16; off; off >>= 1) acc += __shfl_xor_sync(~0u, acc, off);
        if (l == 0) g_c[row] = -0.5f * acc;
    }
}

// ---------------- c_n general fallback (correctness only; no-ops on bench input) ----------------
__global__ void __launch_bounds__(256) k_c_general(const float* __restrict__ means,
                                                   const float* __restrict__ P) {
    if (g_identity) return;
    __shared__ float msm[8][DD];
    int w = threadIdx.x >> 5, l = threadIdx.x & 31;
    for (int j = 0; j < 16; j++) {
        int row = blockIdx.x * 128 + w * 16 + j;
        const float* mr = means + (size_t)row * DD;
        for (int i = l; i < DD; i += 32) msm[w][i] = mr[i];
        __syncwarp();
        float a = 0.f;
        for (int col = l; col < DD; col += 32) {
            float s = 0.f;
            for (int i = 0; i < DD; i++) s += msm[w][i] * P[i * DD + col];
            a += s * msm[w][col];
        }
#pragma unroll
        for (int off = 16; off; off >>= 1) a += __shfl_xor_sync(~0u, a, off);
        if (l == 0) g_c[row] = -0.5f * a;
        __syncwarp();
    }
}

// ---------------- flash pass: logits + online softmax + weighted mean partials ----------------
// grid (SPLIT, BB), 256 threads. Thread t owns output dim t for the accumulator.
__global__ void __launch_bounds__(256) k_flash(const float* __restrict__ means,
                                               const int* __restrict__ niter, int iter) {
    if (iter >= *niter) return;
    int b = blockIdx.y, s = blockIdx.x;
    if (g_conv[b]) return;

    int t = threadIdx.x, w = t >> 5, l = t & 31;
    int d0 = 4 * l, d1 = 128 + 4 * l;

    const float* yb = g_y + b * DD;
    float4 y0 = *(const float4*)(yb + d0);
    float4 y1 = *(const float4*)(yb + d1);

    const float* mb = means + (size_t)b * NN * DD;
    const float* cb = g_c + b * NN;

    __shared__ float logit_sm[32];
    __shared__ float p_sm[32];

    float M = NEG_HUGE, S = 0.f, num = 0.f;
    int row0 = s * CH;

    for (int tile = 0; tile < NTILES; tile++) {
        int tb = row0 + tile * 32;

        // --- dot phase: warp w handles rows tb + w + 8k ---
        float acc[4];
#pragma unroll
        for (int k = 0; k < 4; k++) {
            const float* mr = mb + (size_t)(tb + w + 8 * k) * DD;
            float4 a = *(const float4*)(mr + d0);
            float4 c4 = *(const float4*)(mr + d1);
            acc[k] = a.x * y0.x + a.y * y0.y + a.z * y0.z + a.w * y0.w +
                     c4.x * y1.x + c4.y * y1.y + c4.z * y1.z + c4.w * y1.w;
        }
#pragma unroll
        for (int k = 0; k < 4; k++) {
            float v = acc[k];
#pragma unroll
            for (int off = 16; off; off >>= 1) v += __shfl_xor_sync(~0u, v, off);
            if (l == 0) logit_sm[w + 8 * k] = v + cb[tb + w + 8 * k];
        }
        __syncthreads();

        // --- softmax update (replicated per thread; identical results) ---
        float tm = M;
#pragma unroll
        for (int r = 0; r < 32; r++) tm = fmaxf(tm, logit_sm[r]);
        if (t < 32) p_sm[t] = expf(logit_sm[t] - tm);
        __syncthreads();

        if (tm != M) {
            float scale = expf(M - tm);   // M == NEG_HUGE on first tile -> 0
            num *= scale;
            S *= scale;
            M = tm;
        }
        float ts = 0.f;
        const float* mc = mb + (size_t)tb * DD + t;  // column t of tile (L1/L2 hit)
#pragma unroll 8
        for (int r = 0; r < 32; r++) {
            float p = p_sm[r];
            ts += p;
            num = fmaf(p, mc[r * DD], num);
        }
        S += ts;
        __syncthreads();
    }

    float* part = g_part + (size_t)(b * SPLIT + s) * (DD + 2);
    if (t == 0) { part[0] = M; part[1] = S; }
    part[2 + t] = num;
}

// ---------------- combine partials -> z_new; convergence check; next y ----------------
__global__ void __launch_bounds__(256) k_combine(const float* __restrict__ P,
                                                 const int* __restrict__ niter, int iter) {
    if (iter >= *niter) return;
    int b = blockIdx.x, t = threadIdx.x;
    if (g_conv[b]) return;

    const float* base = g_part + (size_t)b * SPLIT * (DD + 2);
    float Mg = NEG_HUGE;
    float Ms[SPLIT];
#pragma unroll
    for (int s = 0; s < SPLIT; s++) {
        Ms[s] = base[s * (DD + 2)];
        Mg = fmaxf(Mg, Ms[s]);
    }
    float S = 0.f, num = 0.f;
#pragma unroll
    for (int s = 0; s < SPLIT; s++) {
        float e = expf(Ms[s] - Mg);
        S += base[s * (DD + 2) + 1] * e;
        num += base[s * (DD + 2) + 2 + t] * e;
    }
    float z = num / S;

    float old = g_z[b * DD + t];
    int eq = __syncthreads_and(__float_as_int(z) == __float_as_int(old));
    g_z[b * DD + t] = z;
    if (eq) {
        if (t == 0) g_conv[b] = 1;   // fixed point reached bitwise; later iters identical
        return;
    }

    if (iter + 1 < *niter) {
        __shared__ float zs[DD];
        zs[t] = z;
        __syncthreads();
        float acc = 0.f;
#pragma unroll 8
        for (int i = 0; i < DD; i++)
            acc += zs[i] * (P[i * DD + t] + P[t * DD + i]);
        g_y[b * DD + t] = 0.5f * acc;
    }
}

// ---------------- writeout ----------------
__global__ void k_out(float* __restrict__ out) {
    int i = blockIdx.x * blockDim.x + threadIdx.x;
    out[i] = g_z[i];
}

// ---------------- launch ----------------
extern "C" void kernel_launch(void* const* d_in, const int* in_sizes, int n_in,
                              void* d_out, int out_size) {
    // metadata order: x (unused), z, means, precision, iterations
    const float* z_in  = (const float*)d_in[1];
    const float* means = (const float*)d_in[2];
    const float* P     = (const float*)d_in[3];

    const int* niter;
    if (n_in >= 5) {
        niter = (const int*)d_in[4];
    } else {
        void* p = nullptr;
        cudaGetSymbolAddress(&p, g_ten);
        niter = (const int*)p;
    }

    k_init<<<1, 256>>>(z_in);
    k_check<<<(DD * DD) / (256 * 4), 256>>>(P);
    k_y<<<BB, 256>>>(P);
    k_c_fast<<<(BB * NN) / 32, 256>>>(means);
    k_c_general<<<(BB * NN) / 128, 256>>>(means, P);

    for (int it = 0; it < 10; it++) {
        k_flash<<<dim3(SPLIT, BB), 256>>>(means, niter, it);
        k_combine<<<BB, 256>>>(P, niter, it);
    }
    k_out<<<BB, 256>>>((float*)d_out);
}

// round 6
// speedup vs baseline: 1.2051x; 1.2051x over previous
#include <cuda_runtime.h>
#include <math.h>

#define BB 64
#define NN 4096
#define DD 256
#define SPLIT 8
#define CH (NN / SPLIT)     // 512 rows per full-mode flash CTA

#define NEG_HUGE (-1.0e38f)
#define T_PRUNE 48.0f       // prune threshold; certified margin = T_PRUNE - 32

// ---------------- scratch (device globals; no allocation allowed) ----------------
__device__ float g_c[BB * NN];                    // -0.5 * m^T P m
__device__ float g_z[BB * DD];                    // current z
__device__ float g_y[BB * DD];                    // y = 0.5 (P+P^T) z  (== z when P==I)
__device__ float g_part[BB * SPLIT * (DD + 2)];   // per-split partials: [M, S, num[256]]
__device__ float g_logits[BB * NN];               // logits from the last FULL pass
__device__ float g_zref[BB * DD];                 // z at active-set build time
__device__ int   g_act[BB * NN];                  // compacted active row indices
__device__ int   g_nact[BB];                      // active counts
__device__ int   g_usefull[BB];                   // 1 -> next flash runs full (and rebuilds)
__device__ int   g_rmax[BB];                      // max ||m_n||^2 per b (float bits)
__device__ int   g_identity;                      // 1 if P == I
__device__ int   g_conv[BB];                      // per-b bitwise-converged flags
__device__ int   g_ten = 10;                      // fallback iteration count

// ---------------- init ----------------
__global__ void k_init(const float* __restrict__ z_in) {
    int t = threadIdx.x;
    if (t == 0) g_identity = 1;
    if (t < BB) { g_conv[t] = 0; g_usefull[t] = 1; g_rmax[t] = 0; g_nact[t] = 0; }
    for (int i = t; i < BB * DD; i += blockDim.x) g_z[i] = z_in[i];
}

// ---------------- check P == eye(D) ----------------
__global__ void k_check(const float* __restrict__ P) {
    int idx = blockIdx.x * blockDim.x + threadIdx.x;
    bool ok = true;
#pragma unroll
    for (int e = 0; e < 4; e++) {
        int q = idx * 4 + e;
        int i = q >> 8, j = q & 255;
        ok &= (P[q] == (i == j ? 1.0f : 0.0f));
    }
    int allok = __syncthreads_and((int)ok);
    if (!allok && threadIdx.x == 0) g_identity = 0;
}

// ---------------- y = 0.5 (P + P^T) z  (one CTA per b; exact for P==I) ----------------
__global__ void k_y(const float* __restrict__ P) {
    int b = blockIdx.x, t = threadIdx.x;
    __shared__ float zs[DD];
    zs[t] = g_z[b * DD + t];
    __syncthreads();
    float acc = 0.f;
#pragma unroll 8
    for (int i = 0; i < DD; i++)
        acc += zs[i] * (P[i * DD + t] + P[t * DD + i]);
    g_y[b * DD + t] = 0.5f * acc;
}

// ---------------- c_n general fallback (only when P != I) ----------------
__global__ void __launch_bounds__(256) k_c_general(const float* __restrict__ means,
                                                   const float* __restrict__ P) {
    if (g_identity) return;
    __shared__ float msm[8][DD];
    int w = threadIdx.x >> 5, l = threadIdx.x & 31;
    for (int j = 0; j < 16; j++) {
        int row = blockIdx.x * 128 + w * 16 + j;
        const float* mr = means + (size_t)row * DD;
        for (int i = l; i < DD; i += 32) msm[w][i] = mr[i];
        __syncwarp();
        float a = 0.f;
        for (int col = l; col < DD; col += 32) {
            float s = 0.f;
            for (int i = 0; i < DD; i++) s += msm[w][i] * P[i * DD + col];
            a += s * msm[w][col];
        }
#pragma unroll
        for (int off = 16; off; off >>= 1) a += __shfl_xor_sync(~0u, a, off);
        if (l == 0) g_c[row] = -0.5f * a;
        __syncwarp();
    }
}

// ---------------- flash: full OR pruned pass, per-b mode flag ----------------
// grid (SPLIT, BB), 256 threads. Thread t owns output dim t for the accumulator.
__global__ void __launch_bounds__(256) k_flash(const float* __restrict__ means,
                                               const int* __restrict__ niter, int iter) {
    if (iter >= *niter) return;
    int b = blockIdx.y, s = blockIdx.x;
    if (g_conv[b]) return;
    const int full = g_usefull[b];

    int t = threadIdx.x, w = t >> 5, l = t & 31;
    int d0 = 4 * l, d1 = 128 + 4 * l;

    const float* yb = g_y + b * DD;
    float4 y0 = *(const float4*)(yb + d0);
    float4 y1 = *(const float4*)(yb + d1);

    const float* mb = means + (size_t)b * NN * DD;
    const float* cb = g_c + b * NN;
    const int*   ab = g_act + b * NN;
    float*       lb = g_logits + b * NN;

    const bool c_inline = full && (iter == 0) && g_identity;

    __shared__ float logit_sm[32];
    __shared__ float p_sm[32];
    __shared__ int   ridx[32];

    float M = NEG_HUGE, S = 0.f, num = 0.f;
    float wmax = 0.f;

    int n0, n1;
    if (full) { n0 = s * CH; n1 = n0 + CH; }
    else { int cnt = g_nact[b]; n0 = (s * cnt) / SPLIT; n1 = ((s + 1) * cnt) / SPLIT; }

    for (int base = n0; base < n1; base += 32) {
        if (t < 32) {
            int row = 0;
            if (full) row = base + t;
            else if (base + t < n1) row = ab[base + t];
            ridx[t] = row;   // clamped to 0 for padding lanes (p will be 0)
        }
        __syncthreads();

        // --- dot phase: warp w handles tile lanes w + 8k ---
#pragma unroll
        for (int k = 0; k < 4; k++) {
            int li = w + 8 * k;
            bool valid = (base + li < n1);
            int row = ridx[li];
            const float* mr = mb + (size_t)row * DD;
            float4 a  = *(const float4*)(mr + d0);
            float4 c4 = *(const float4*)(mr + d1);
            float dot = a.x * y0.x + a.y * y0.y + a.z * y0.z + a.w * y0.w +
                        c4.x * y1.x + c4.y * y1.y + c4.z * y1.z + c4.w * y1.w;
            float qq = 0.f;
            if (c_inline)
                qq = a.x * a.x + a.y * a.y + a.z * a.z + a.w * a.w +
                     c4.x * c4.x + c4.y * c4.y + c4.z * c4.z + c4.w * c4.w;
#pragma unroll
            for (int off = 16; off; off >>= 1) {
                dot += __shfl_xor_sync(~0u, dot, off);
                if (c_inline) qq += __shfl_xor_sync(~0u, qq, off);
            }
            if (l == 0) {
                float lg;
                if (c_inline) {
                    float c = -0.5f * qq;
                    g_c[b * NN + row] = c;
                    wmax = fmaxf(wmax, qq);
                    lg = c + dot;
                } else {
                    lg = cb[row] + dot;
                }
                if (!valid) lg = NEG_HUGE;
                logit_sm[li] = lg;
                if (full) lb[row] = lg;     // enable rebuild after any full pass
            }
        }
        __syncthreads();

        // --- online softmax update (replicated; deterministic) ---
        float tm = M;
#pragma unroll
        for (int r = 0; r < 32; r++) tm = fmaxf(tm, logit_sm[r]);
        if (t < 32) p_sm[t] = expf(logit_sm[t] - tm);
        __syncthreads();

        if (tm != M) {
            float sc = expf(M - tm);   // M == NEG_HUGE on first tile -> 0
            num *= sc; S *= sc; M = tm;
        }
        float ts = 0.f;
#pragma unroll 8
        for (int r = 0; r < 32; r++) {
            float p = p_sm[r];
            ts += p;
            num = fmaf(p, mb[(size_t)ridx[r] * DD + t], num);   // L1-hot re-read
        }
        S += ts;
        __syncthreads();
    }

    if (c_inline && l == 0)
        atomicMax(&g_rmax[b], __float_as_int(wmax));   // norms^2 > 0: int cmp valid

    float* part = g_part + (size_t)(b * SPLIT + s) * (DD + 2);
    if (t == 0) { part[0] = M; part[1] = S; }
    part[2 + t] = num;
}

// ---------------- combine: z update, convergence, next y, rebuild + drift cert ----------------
__global__ void __launch_bounds__(256) k_combine(const float* __restrict__ P,
                                                 const int* __restrict__ niter, int iter) {
    if (iter >= *niter) return;
    int b = blockIdx.x, t = threadIdx.x, w = t >> 5, l = t & 31;
    if (g_conv[b]) return;
    const int wasfull = g_usefull[b];

    const float* base = g_part + (size_t)b * SPLIT * (DD + 2);
    float Mg = NEG_HUGE, Ms[SPLIT];
#pragma unroll
    for (int s = 0; s < SPLIT; s++) { Ms[s] = base[s * (DD + 2)]; Mg = fmaxf(Mg, Ms[s]); }
    float S = 0.f, num = 0.f;
#pragma unroll
    for (int s = 0; s < SPLIT; s++) {
        float e = expf(Ms[s] - Mg);
        S   += base[s * (DD + 2) + 1] * e;
        num += base[s * (DD + 2) + 2 + t] * e;
    }
    float z = num / S;

    float old = g_z[b * DD + t];
    int eq = __syncthreads_and(__float_as_int(z) == __float_as_int(old));
    g_z[b * DD + t] = z;
    if (eq) { if (t == 0) g_conv[b] = 1; return; }   // fixed point: later iters identical

    const int identity = g_identity;
    if (iter + 1 < *niter) {
        if (identity) {
            g_y[b * DD + t] = z;                     // y == z exactly for P == I
        } else {
            __shared__ float zs[DD];
            zs[t] = z;
            __syncthreads();
            float acc = 0.f;
#pragma unroll 8
            for (int i = 0; i < DD; i++)
                acc += zs[i] * (P[i * DD + t] + P[t * DD + i]);
            g_y[b * DD + t] = 0.5f * acc;
        }
    }
    if (!identity) { if (t == 0) g_usefull[b] = 1; return; }   // never prune general P

    // --- rebuild active set from the full pass that just ran ---
    __shared__ int cnts[256];
    __shared__ float sred[8];
    float zr;
    if (wasfull) {
        float th = Mg - T_PRUNE;
        const float* lg = g_logits + b * NN;
        float myl[16]; int c = 0;
#pragma unroll
        for (int j = 0; j < 16; j++) { myl[j] = lg[t * 16 + j]; c += (myl[j] >= th); }
        cnts[t] = c;
        __syncthreads();
        for (int off = 1; off < 256; off <<= 1) {    // Hillis-Steele inclusive scan
            int v = (t >= off) ? cnts[t - off] : 0;
            __syncthreads();
            cnts[t] += v;
            __syncthreads();
        }
        int pos = cnts[t] - c;                        // exclusive prefix: deterministic order
        int* act = g_act + b * NN;
#pragma unroll
        for (int j = 0; j < 16; j++)
            if (myl[j] >= th) act[pos++] = t * 16 + j;
        if (t == 255) g_nact[b] = cnts[255];
        g_zref[b * DD + t] = old;                     // z that produced these logits
        zr = old;
    } else {
        zr = g_zref[b * DD + t];
    }

    // --- drift certificate: pruning valid iff 2*R*||z_next - zref|| <= T - 32 ---
    float d = z - zr; d *= d;
#pragma unroll
    for (int off = 16; off; off >>= 1) d += __shfl_xor_sync(~0u, d, off);
    if (l == 0) sred[w] = d;
    __syncthreads();
    if (t == 0) {
        float dd = 0.f;
#pragma unroll
        for (int i = 0; i < 8; i++) dd += sred[i];
        float R2 = __int_as_float(g_rmax[b]);
        float mar = T_PRUNE - 32.0f;
        g_usefull[b] = (4.0f * R2 * dd > mar * mar) ? 1 : 0;
    }
}

// ---------------- writeout ----------------
__global__ void k_out(float* __restrict__ out) {
    int i = blockIdx.x * blockDim.x + threadIdx.x;
    out[i] = g_z[i];
}

// ---------------- launch ----------------
extern "C" void kernel_launch(void* const* d_in, const int* in_sizes, int n_in,
                              void* d_out, int out_size) {
    // metadata order: x (unused), z, means, precision, iterations
    const float* z_in  = (const float*)d_in[1];
    const float* means = (const float*)d_in[2];
    const float* P     = (const float*)d_in[3];

    const int* niter;
    if (n_in >= 5) {
        niter = (const int*)d_in[4];
    } else {
        void* p = nullptr;
        cudaGetSymbolAddress(&p, g_ten);
        niter = (const int*)p;
    }

    k_init<<<1, 256>>>(z_in);
    k_check<<<(DD * DD) / (256 * 4), 256>>>(P);
    k_y<<<BB, 256>>>(P);
    k_c_general<<<(BB * NN) / 128, 256>>>(means, P);   // no-op when P == I

    for (int it = 0; it < 10; it++) {
        k_flash<<<dim3(SPLIT, BB), 256>>>(means, niter, it);
        k_combine<<<BB, 256>>>(P, niter, it);
    }
    k_out<<<BB, 256>>>((float*)d_out);
}